// round 2
// baseline (speedup 1.0000x reference)
#include <cuda_runtime.h>

// Haar DWT2: input [8, 32, 512, 512] f32 -> output [8, 4, 32, 256, 256] f32.
// Subbands stacked at axis 1: (LL, LH, HL, HH).
//
// Each thread processes a 2(row) x 4(col) input block -> 2 output pixels per
// subband. Loads: 2x float4 (coalesced). Stores: 4x float2 (coalesced per
// subband plane).

#define H 512
#define W 512
#define H2 256
#define W2 256
#define CCH 32          // channels
#define PLANE_IN (H * W)        // 262144
#define PLANE_OUT (H2 * W2)     // 65536

__global__ __launch_bounds__(128) void haar_dwt2_kernel(
    const float* __restrict__ in, float* __restrict__ out)
{
    const int tx = threadIdx.x;          // 0..127 : w-pair-of-2 index (covers 4 input cols)
    const int h2 = blockIdx.x;           // 0..255
    const int bc = blockIdx.y;           // 0..255 : b*32 + c
    const int b = bc >> 5;
    const int c = bc & 31;

    const float* src = in + (size_t)bc * PLANE_IN + (size_t)(2 * h2) * W + 4 * tx;
    const float4 r0 = *reinterpret_cast<const float4*>(src);
    const float4 r1 = *reinterpret_cast<const float4*>(src + W);

    // pixel 0: cols 4tx, 4tx+1 ; pixel 1: cols 4tx+2, 4tx+3
    // pywt haar: LL=(a+b+c+d)/2, LH=(a+b-c-d)/2, HL=(a-b+c-d)/2, HH=(a-b-c+d)/2
    // where a=x00,b=x01,c=x10,d=x11
    float2 LL, LH, HL, HH;
    {
        const float a = r0.x, bb = r0.y, cc = r1.x, dd = r1.y;
        LL.x = (a + bb + cc + dd) * 0.5f;
        LH.x = (a + bb - cc - dd) * 0.5f;
        HL.x = (a - bb + cc - dd) * 0.5f;
        HH.x = (a - bb - cc + dd) * 0.5f;
    }
    {
        const float a = r0.z, bb = r0.w, cc = r1.z, dd = r1.w;
        LL.y = (a + bb + cc + dd) * 0.5f;
        LH.y = (a + bb - cc - dd) * 0.5f;
        HL.y = (a - bb + cc - dd) * 0.5f;
        HH.y = (a - bb - cc + dd) * 0.5f;
    }

    // out layout: [b][s][c][h2][w2] with s in {0:LL,1:LH,2:HL,3:HH}
    const size_t base = ((size_t)(b * 4) * CCH + c) * PLANE_OUT
                        + (size_t)h2 * W2 + 2 * tx;
    float* o = out + base;
    const size_t sstride = (size_t)CCH * PLANE_OUT;   // one subband plane group
    *reinterpret_cast<float2*>(o) = LL;
    *reinterpret_cast<float2*>(o + sstride) = LH;
    *reinterpret_cast<float2*>(o + 2 * sstride) = HL;
    *reinterpret_cast<float2*>(o + 3 * sstride) = HH;
}

extern "C" void kernel_launch(void* const* d_in, const int* in_sizes, int n_in,
                              void* d_out, int out_size)
{
    const float* in = (const float*)d_in[0];
    float* out = (float*)d_out;
    dim3 grid(H2, 8 * CCH);   // (256 h-pairs, 256 b*c planes)
    haar_dwt2_kernel<<<grid, 128>>>(in, out);
}

// round 3
// speedup vs baseline: 1.0031x; 1.0031x over previous
#include <cuda_runtime.h>

// Haar DWT2: input [8, 32, 512, 512] f32 -> output [8, 4, 32, 256, 256] f32.
// Subbands stacked at axis 1: (LL, LH, HL, HH).
//
// Each thread processes a 2(row) x 8(col) input block -> 4 output pixels per
// subband. Loads: 4x float4 streaming (coalesced). Stores: 4x float4 streaming
// (one per subband plane, coalesced).

#define H 512
#define W 512
#define H2 256
#define W2 256
#define CCH 32                  // channels
#define PLANE_IN (H * W)        // 262144
#define PLANE_OUT (H2 * W2)     // 65536

__global__ __launch_bounds__(128) void haar_dwt2_kernel(
    const float* __restrict__ in, float* __restrict__ out)
{
    const int t  = threadIdx.x;          // 0..127
    const int wv = t & 63;               // 0..63 : 8-col group index within row
    const int hr = t >> 6;               // 0..1  : which h2 row within this block
    const int h2 = blockIdx.x * 2 + hr;  // 0..255
    const int bc = blockIdx.y;           // 0..255 : b*32 + c
    const int b  = bc >> 5;
    const int c  = bc & 31;

    const float* src = in + (size_t)bc * PLANE_IN + (size_t)(2 * h2) * W + 8 * wv;
    // Front-batched independent loads (MLP=4), streaming (no reuse).
    const float4 r0a = __ldcs(reinterpret_cast<const float4*>(src));
    const float4 r0b = __ldcs(reinterpret_cast<const float4*>(src + 4));
    const float4 r1a = __ldcs(reinterpret_cast<const float4*>(src + W));
    const float4 r1b = __ldcs(reinterpret_cast<const float4*>(src + W + 4));

    // pywt haar: LL=(a+b+c+d)/2, LH=(a+b-c-d)/2, HL=(a-b+c-d)/2, HH=(a-b-c+d)/2
    float4 LL, LH, HL, HH;
    {
        const float a = r0a.x, bb = r0a.y, cc = r1a.x, dd = r1a.y;
        LL.x = (a + bb + cc + dd) * 0.5f;
        LH.x = (a + bb - cc - dd) * 0.5f;
        HL.x = (a - bb + cc - dd) * 0.5f;
        HH.x = (a - bb - cc + dd) * 0.5f;
    }
    {
        const float a = r0a.z, bb = r0a.w, cc = r1a.z, dd = r1a.w;
        LL.y = (a + bb + cc + dd) * 0.5f;
        LH.y = (a + bb - cc - dd) * 0.5f;
        HL.y = (a - bb + cc - dd) * 0.5f;
        HH.y = (a - bb - cc + dd) * 0.5f;
    }
    {
        const float a = r0b.x, bb = r0b.y, cc = r1b.x, dd = r1b.y;
        LL.z = (a + bb + cc + dd) * 0.5f;
        LH.z = (a + bb - cc - dd) * 0.5f;
        HL.z = (a - bb + cc - dd) * 0.5f;
        HH.z = (a - bb - cc + dd) * 0.5f;
    }
    {
        const float a = r0b.z, bb = r0b.w, cc = r1b.z, dd = r1b.w;
        LL.w = (a + bb + cc + dd) * 0.5f;
        LH.w = (a + bb - cc - dd) * 0.5f;
        HL.w = (a - bb + cc - dd) * 0.5f;
        HH.w = (a - bb - cc + dd) * 0.5f;
    }

    // out layout: [b][s][c][h2][w2] with s in {0:LL,1:LH,2:HL,3:HH}
    const size_t base = ((size_t)(b * 4) * CCH + c) * PLANE_OUT
                        + (size_t)h2 * W2 + 4 * wv;
    float* o = out + base;
    const size_t sstride = (size_t)CCH * PLANE_OUT;   // subband group stride
    __stcs(reinterpret_cast<float4*>(o), LL);
    __stcs(reinterpret_cast<float4*>(o + sstride), LH);
    __stcs(reinterpret_cast<float4*>(o + 2 * sstride), HL);
    __stcs(reinterpret_cast<float4*>(o + 3 * sstride), HH);
}

extern "C" void kernel_launch(void* const* d_in, const int* in_sizes, int n_in,
                              void* d_out, int out_size)
{
    const float* in = (const float*)d_in[0];
    float* out = (float*)d_out;
    dim3 grid(H2 / 2, 8 * CCH);   // (128 row-pair groups, 256 b*c planes)
    haar_dwt2_kernel<<<grid, 128>>>(in, out);
}